// round 7
// baseline (speedup 1.0000x reference)
#include <cuda_runtime.h>
#include <math.h>

#define BB 64
#define HH 1024
#define INN 1024
#define GN_EPS 1e-5f

#define SPLITS 16
#define KCH 64        // K per split
#define KC 32         // smem K tile
#define NG (6 * HH)   // 6144 fused gate columns
#define NBLK 128      // n per block

// Small scratch only (partials live in the out_C output region, overwritten by k3)
__device__ float g_gate[6][BB * HH];          // q,k,v,i,f,o
__device__ float g_ht[BB * HH];
__device__ float g_denom[BB];
__device__ float g_vq[BB];
__device__ unsigned int g_cnt[BB];            // zero-init; self-resetting

__device__ __forceinline__ float sigmoidf_(float x) {
    return 1.0f / (1.0f + expf(-x));
}
__device__ __forceinline__ float softplusf_(float x) {
    return fmaxf(x, 0.0f) + log1pf(expf(-fabsf(x)));
}

// ---- packed f32x2 helpers ----
__device__ __forceinline__ unsigned long long dup2_(float v) {
    unsigned long long r;
    asm("mov.b64 %0, {%1, %1};" : "=l"(r) : "r"(__float_as_uint(v)));
    return r;
}
__device__ __forceinline__ void fma2_(unsigned long long& d,
                                      unsigned long long a,
                                      unsigned long long b) {
    asm("fma.rn.f32x2 %0, %1, %2, %0;" : "+l"(d) : "l"(a), "l"(b));
}
__device__ __forceinline__ float2 unpk_(unsigned long long v) {
    unsigned int lo, hi;
    asm("mov.b64 {%0, %1}, %2;" : "=r"(lo), "=r"(hi) : "l"(v));
    return make_float2(__uint_as_float(lo), __uint_as_float(hi));
}

// ----------------------------------------------------------------------------
// Kernel 1: fused split-K GEMM over all six gates.
// part[sp][b][ng] = sum_{k in split sp} x[b,k] * W_all[ng,k], ng in [0,6144).
// Tile 64m x 128n, K-chunk 64 per split, 128 threads, micro 8m x 8n (f32x2).
// grid = (48 n-blocks, 16 splits) = 768 blocks.
// ----------------------------------------------------------------------------
__global__ __launch_bounds__(128) void k1_gemm_gates(
    const float* __restrict__ x,
    const float* __restrict__ Wq, const float* __restrict__ Wk,
    const float* __restrict__ Wv, const float* __restrict__ Wi,
    const float* __restrict__ Wf, const float* __restrict__ Wo,
    float* __restrict__ part)   // [SPLITS][BB][NG]
{
    const int n0g = blockIdx.x * NBLK;     // global n (tile never straddles a gate: 1024/128=8)
    const int g = n0g >> 10;
    const int nloc0 = n0g & 1023;          // row within the gate's W
    const float* __restrict__ W =
        (g == 0) ? Wq : (g == 1) ? Wk : (g == 2) ? Wv : (g == 3) ? Wi : (g == 4) ? Wf : Wo;
    const int k0s = blockIdx.y * KCH;

    __shared__ __align__(16) float Xs[KC][68];    // [k][m], 272B stride
    __shared__ __align__(16) float Ws[KC][132];   // [k][n], 528B stride

    const int tid = threadIdx.x;
    const int tx = tid & 15;   // n micro-group: 8 cols
    const int ty = tid >> 4;   // m micro-group: 8 rows

    unsigned long long acc[4][8];   // [m-pair][nj]
#pragma unroll
    for (int i = 0; i < 4; i++)
#pragma unroll
        for (int j = 0; j < 8; j++) acc[i][j] = 0ull;

    for (int kc0 = 0; kc0 < KCH; kc0 += KC) {
        const int k0 = k0s + kc0;
        // X: 64 rows x 8 float4-chunks = 512 chunks, 4/thread
        // W: 128 rows x 8 chunks = 1024 chunks, 8/thread
        float4 xa[4], wa[8];
#pragma unroll
        for (int i = 0; i < 4; i++) {
            const int c = tid + i * 128;
            const int r = c >> 3;
            const int kq = (c & 7) * 4;
            xa[i] = *(const float4*)(x + r * INN + k0 + kq);
        }
#pragma unroll
        for (int i = 0; i < 8; i++) {
            const int c = tid + i * 128;
            const int r = c >> 3;
            const int kq = (c & 7) * 4;
            wa[i] = *(const float4*)(W + (size_t)(nloc0 + r) * INN + k0 + kq);
        }
        __syncthreads();
#pragma unroll
        for (int i = 0; i < 4; i++) {
            const int c = tid + i * 128;
            const int r = c >> 3;
            const int kq = (c & 7) * 4;
            Xs[kq + 0][r] = xa[i].x; Xs[kq + 1][r] = xa[i].y;
            Xs[kq + 2][r] = xa[i].z; Xs[kq + 3][r] = xa[i].w;
        }
#pragma unroll
        for (int i = 0; i < 8; i++) {
            const int c = tid + i * 128;
            const int r = c >> 3;
            const int kq = (c & 7) * 4;
            Ws[kq + 0][r] = wa[i].x; Ws[kq + 1][r] = wa[i].y;
            Ws[kq + 2][r] = wa[i].z; Ws[kq + 3][r] = wa[i].w;
        }
        __syncthreads();

#pragma unroll
        for (int kk = 0; kk < KC; kk++) {
            ulonglong2 A0 = *(const ulonglong2*)&Xs[kk][ty * 8];      // rows 0..3
            ulonglong2 A1 = *(const ulonglong2*)&Xs[kk][ty * 8 + 4];  // rows 4..7
            float4 b0 = *(const float4*)&Ws[kk][tx * 8];
            float4 b1 = *(const float4*)&Ws[kk][tx * 8 + 4];
            const float bs[8] = {b0.x, b0.y, b0.z, b0.w, b1.x, b1.y, b1.z, b1.w};
#pragma unroll
            for (int j = 0; j < 8; j++) {
                const unsigned long long bd = dup2_(bs[j]);
                fma2_(acc[0][j], A0.x, bd);
                fma2_(acc[1][j], A0.y, bd);
                fma2_(acc[2][j], A1.x, bd);
                fma2_(acc[3][j], A1.y, bd);
            }
        }
    }

    // store: rows m = ty*8 + (0..7) == batch index, cols n0g + tx*8 ..
    float* __restrict__ po = part + (size_t)blockIdx.y * BB * NG;
#pragma unroll
    for (int mi = 0; mi < 4; mi++) {
        float va[8], vb[8];
#pragma unroll
        for (int j = 0; j < 8; j++) {
            float2 t = unpk_(acc[mi][j]);
            va[j] = t.x;
            vb[j] = t.y;
        }
        const int m0 = ty * 8 + mi * 2;
        float* r0p = po + (size_t)m0 * NG + n0g + tx * 8;
        float* r1p = po + (size_t)(m0 + 1) * NG + n0g + tx * 8;
        *(float4*)(r0p)     = make_float4(va[0], va[1], va[2], va[3]);
        *(float4*)(r0p + 4) = make_float4(va[4], va[5], va[6], va[7]);
        *(float4*)(r1p)     = make_float4(vb[0], vb[1], vb[2], vb[3]);
        *(float4*)(r1p + 4) = make_float4(vb[4], vb[5], vb[6], vb[7]);
    }
}

// ----------------------------------------------------------------------------
// Kernel 2: combine split-K partials (fixed order => deterministic), apply
// bias + activations, store gates; then n/m update + denom/vq reductions.
// grid = 64 (batch), block = 1024.
// ----------------------------------------------------------------------------
__global__ __launch_bounds__(1024) void k2_combine_nm(
    const float* __restrict__ part,
    const float* __restrict__ bi, const float* __restrict__ bf,
    const float* __restrict__ bo,
    const float* __restrict__ n_prev, const float* __restrict__ m_prev,
    float* __restrict__ out_n, float* __restrict__ out_m)
{
    const int b = blockIdx.x;
    const int tid = threadIdx.x;
    const int h = b * HH + tid;

    float y[6];
#pragma unroll
    for (int g = 0; g < 6; g++) {
        float s = 0.0f;
#pragma unroll
        for (int sp = 0; sp < SPLITS; sp++)
            s += part[((size_t)sp * BB + b) * NG + g * HH + tid];
        y[g] = s;
    }

    const float qv = y[0];
    const float kv = y[1];
    const float vv = y[2];
    const float iv = softplusf_(y[3] + bi[tid]);
    const float fv = sigmoidf_(y[4] + bf[tid]);
    const float ov = sigmoidf_(y[5] + bo[tid]);

    g_gate[0][h] = qv;
    g_gate[1][h] = kv;
    g_gate[2][h] = vv;
    g_gate[3][h] = iv;
    g_gate[4][h] = fv;
    g_gate[5][h] = ov;

    const float nv = fmaf(fv, n_prev[h], iv * kv);
    const float mv = fmaxf(fv * m_prev[h], iv);
    out_n[h] = nv;
    out_m[h] = mv;

    float snq = nv * qv;
    float svq = vv * qv;
#pragma unroll
    for (int s = 16; s > 0; s >>= 1) {
        snq += __shfl_xor_sync(0xFFFFFFFFu, snq, s);
        svq += __shfl_xor_sync(0xFFFFFFFFu, svq, s);
    }
    __shared__ float p1[32], p2[32];
    const int warp = tid >> 5, lane = tid & 31;
    if (lane == 0) { p1[warp] = snq; p2[warp] = svq; }
    __syncthreads();
    if (warp == 0) {
        float a = p1[lane], c = p2[lane];
#pragma unroll
        for (int s = 16; s > 0; s >>= 1) {
            a += __shfl_xor_sync(0xFFFFFFFFu, a, s);
            c += __shfl_xor_sync(0xFFFFFFFFu, c, s);
        }
        if (lane == 0) {
            g_denom[b] = fmaxf(a, 1.0f);
            g_vq[b] = c;
        }
    }
}

// ----------------------------------------------------------------------------
// Kernel 3: streaming 512 MB + fused GroupNorm epilogue (last block per batch)
// grid = (64 rowblocks, 64 b), block = 512 (16 warps, 1 warp/row)
// Overwrites ALL of out_C (including the region k1 used as scratch).
// ----------------------------------------------------------------------------
__global__ __launch_bounds__(512) void k3_c_update(
    const float* __restrict__ C_prev, float* __restrict__ out_C,
    const float* __restrict__ gn_w, const float* __restrict__ gn_b,
    float* __restrict__ out_h)
{
    const int b = blockIdx.y;
    const int r0 = blockIdx.x * 16;
    const int tid = threadIdx.x;

    __shared__ float sq[HH];
    __shared__ float sv[HH];
#pragma unroll
    for (int j = 0; j < 2; j++) {
        const int idx = tid + j * 512;
        sq[idx] = g_gate[0][b * HH + idx];
        sv[idx] = g_gate[2][b * HH + idx];
    }
    __syncthreads();

    const int warp = tid >> 5;
    const int lane = tid & 31;
    const int r = r0 + warp;

    const float f  = g_gate[4][b * HH + r];
    const float ik = g_gate[3][b * HH + r] * g_gate[1][b * HH + r];

    const float* __restrict__ cp = C_prev + ((size_t)b * HH + r) * HH;
    float* __restrict__ co = out_C + ((size_t)b * HH + r) * HH;

    float4 p[8];
#pragma unroll
    for (int j = 0; j < 8; j++)
        p[j] = __ldcs((const float4*)(cp + lane * 4 + j * 128));

    float dot = 0.0f;
#pragma unroll
    for (int j = 0; j < 8; j++) {
        const int c = lane * 4 + j * 128;
        float4 vv = *(const float4*)(sv + c);
        float4 qq = *(const float4*)(sq + c);
        float4 o;
        o.x = fmaf(f, p[j].x, ik * vv.x);
        o.y = fmaf(f, p[j].y, ik * vv.y);
        o.z = fmaf(f, p[j].z, ik * vv.z);
        o.w = fmaf(f, p[j].w, ik * vv.w);
        __stcs((float4*)(co + c), o);
        dot = fmaf(p[j].x, qq.x, dot);
        dot = fmaf(p[j].y, qq.y, dot);
        dot = fmaf(p[j].z, qq.z, dot);
        dot = fmaf(p[j].w, qq.w, dot);
    }
#pragma unroll
    for (int s = 16; s > 0; s >>= 1)
        dot += __shfl_xor_sync(0xFFFFFFFFu, dot, s);
    if (lane == 0) {
        g_ht[b * HH + r] = fmaf(f, dot, ik * g_vq[b]);
        __threadfence();
    }

    // ---- last-block-per-batch GroupNorm epilogue ----
    __syncthreads();
    __shared__ unsigned int s_old;
    if (tid == 0)
        s_old = atomicAdd(&g_cnt[b], 1u);
    __syncthreads();
    if (s_old != 63u) return;

    __threadfence();
    const float inv_d = 1.0f / g_denom[b];

    float xv[2];
    float s = 0.0f, s2 = 0.0f;
#pragma unroll
    for (int j = 0; j < 2; j++) {
        const int h = tid + j * 512;
        const float v = __ldcg(&g_ht[b * HH + h]) * inv_d;
        xv[j] = v;
        s += v;
        s2 = fmaf(v, v, s2);
    }
#pragma unroll
    for (int st = 16; st > 0; st >>= 1) {
        s  += __shfl_xor_sync(0xFFFFFFFFu, s, st);
        s2 += __shfl_xor_sync(0xFFFFFFFFu, s2, st);
    }
    __shared__ float p1[16], p2[16];
    __shared__ float mu_s, rstd_s;
    if (lane == 0) { p1[warp] = s; p2[warp] = s2; }
    __syncthreads();
    if (warp == 0) {
        float a = (lane < 16) ? p1[lane] : 0.0f;
        float c = (lane < 16) ? p2[lane] : 0.0f;
#pragma unroll
        for (int st = 8; st > 0; st >>= 1) {
            a += __shfl_xor_sync(0xFFFFFFFFu, a, st);
            c += __shfl_xor_sync(0xFFFFFFFFu, c, st);
        }
        if (lane == 0) {
            const float mu = a * (1.0f / HH);
            float var = c * (1.0f / HH) - mu * mu;
            var = fmaxf(var, 0.0f);
            mu_s = mu;
            rstd_s = rsqrtf(var + GN_EPS);
        }
    }
    __syncthreads();
    const float mu = mu_s, rstd = rstd_s;

#pragma unroll
    for (int j = 0; j < 2; j++) {
        const int h = tid + j * 512;
        const float norm = fmaf((xv[j] - mu) * rstd, gn_w[h], gn_b[h]);
        out_h[b * HH + h] = g_gate[5][b * HH + h] * norm;
    }
    if (tid == 0) g_cnt[b] = 0u;
}

// ----------------------------------------------------------------------------
extern "C" void kernel_launch(void* const* d_in, const int* in_sizes, int n_in,
                              void* d_out, int out_size)
{
    const float* x      = (const float*)d_in[0];
    const float* C_prev = (const float*)d_in[1];
    const float* n_prev = (const float*)d_in[2];
    const float* m_prev = (const float*)d_in[3];
    const float* Wq     = (const float*)d_in[4];
    const float* Wk     = (const float*)d_in[5];
    const float* Wv     = (const float*)d_in[6];
    const float* Wi     = (const float*)d_in[7];
    const float* bi     = (const float*)d_in[8];
    const float* Wf     = (const float*)d_in[9];
    const float* bf     = (const float*)d_in[10];
    const float* Wo     = (const float*)d_in[11];
    const float* bo     = (const float*)d_in[12];
    const float* gn_w   = (const float*)d_in[13];
    const float* gn_b   = (const float*)d_in[14];

    float* out   = (float*)d_out;
    float* out_h = out;                                   // [B,H]
    float* out_C = out_h + BB * HH;                       // [B,H,H]
    float* out_n = out_C + (size_t)BB * HH * HH;          // [B,H]
    float* out_m = out_n + BB * HH;                       // [B,H]

    // Split-K partials live in the front of out_C (25 MB of its 256 MB);
    // k3 fully overwrites out_C afterwards, so this is pure scratch reuse.
    float* part = out_C;

    dim3 g1(NG / NBLK, SPLITS);
    k1_gemm_gates<<<g1, 128>>>(x, Wq, Wk, Wv, Wi, Wf, Wo, part);
    k2_combine_nm<<<BB, 1024>>>(part, bi, bf, bo, n_prev, m_prev, out_n, out_m);
    dim3 g3(HH / 16, BB);
    k3_c_update<<<g3, 512>>>(C_prev, out_C, gn_w, gn_b, out_h);
}